// round 8
// baseline (speedup 1.0000x reference)
#include <cuda_runtime.h>
#include <cuda_bf16.h>
#include <cstdint>

// Problem constants
#define NB   16
#define NPTS 65536
#define NPAT 64      // NUM_PATCHES
#define KNN  32      // PATCH_SIZE

// FPS: one 8-CTA cluster per batch, 1024 threads, 8 pts/thread
#define FPS_BLKS   8
#define FPS_THR    1024
#define FPS_PPT    8

typedef unsigned long long u64;
typedef unsigned int u32;

// Scratch (allocation-free rule: __device__ global)
__device__ float4 g_pts4[NB * NPTS];   // x,y,z,|p|^2 (FMA-chain p2)

// ---- packed f32x2 helpers (per-lane RN => bit-identical to scalar) ----
__device__ __forceinline__ u64 pk2(float a, float b) {
    u64 r; asm("mov.b64 %0,{%1,%2};" : "=l"(r) : "f"(a), "f"(b)); return r;
}
__device__ __forceinline__ void upk2(u64 v, float& a, float& b) {
    asm("mov.b64 {%0,%1},%2;" : "=f"(a), "=f"(b) : "l"(v));
}
__device__ __forceinline__ u64 add2(u64 a, u64 b) {
    u64 r; asm("add.rn.f32x2 %0,%1,%2;" : "=l"(r) : "l"(a), "l"(b)); return r;
}
__device__ __forceinline__ u64 mul2(u64 a, u64 b) {
    u64 r; asm("mul.rn.f32x2 %0,%1,%2;" : "=l"(r) : "l"(a), "l"(b)); return r;
}
__device__ __forceinline__ u64 fma2(u64 a, u64 b, u64 c) {
    u64 r; asm("fma.rn.f32x2 %0,%1,%2,%3;" : "=l"(r) : "l"(a), "l"(b), "l"(c)); return r;
}

// ---- cluster / mbarrier helpers ----
__device__ __forceinline__ u32 smem_u32(const void* p) {
    return (u32)__cvta_generic_to_shared(p);
}
__device__ __forceinline__ u32 mapa_u32(u32 laddr, u32 rank) {
    u32 r;
    asm("mapa.shared::cluster.u32 %0, %1, %2;" : "=r"(r) : "r"(laddr), "r"(rank));
    return r;
}
__device__ __forceinline__ void st_cluster_u64(u32 addr, u64 v) {
    asm volatile("st.shared::cluster.u64 [%0], %1;" :: "r"(addr), "l"(v) : "memory");
}
__device__ __forceinline__ void mbar_init(u32 addr, u32 cnt) {
    asm volatile("mbarrier.init.shared.b64 [%0], %1;" :: "r"(addr), "r"(cnt) : "memory");
}
__device__ __forceinline__ void mbar_arrive_cluster(u32 addr) {
    asm volatile("mbarrier.arrive.release.cluster.shared::cluster.b64 _, [%0];"
                 :: "r"(addr) : "memory");
}
__device__ __forceinline__ void mbar_wait_cluster(u32 addr, u32 parity) {
    asm volatile(
        "{\n\t.reg .pred P;\n\t"
        "WAIT_%=:\n\t"
        "mbarrier.try_wait.parity.acquire.cluster.shared::cta.b64 P, [%0], %1;\n\t"
        "@!P bra WAIT_%=;\n\t}"
        :: "r"(addr), "r"(parity) : "memory");
}

// ---------------------------------------------------------------------------
// Kernel 1: FPS (prep fused). 8-CTA cluster per batch. Packed f32x2 compute
// (round-3-validated bit-exact). Per-iter all-to-all over DSMEM: push
// (key, coords) to all peers' parity slots, release-arrive on each peer's
// mbarrier, acquire-try_wait, LOCAL reduce. Winner LDG off the critical path.
// ---------------------------------------------------------------------------
__global__ void __launch_bounds__(FPS_THR, 1) __cluster_dims__(FPS_BLKS, 1, 1)
fps_kernel(const float* __restrict__ raw_in,
           float* __restrict__ centers_out /* [NB][NPAT][3] */) {
    const int b    = blockIdx.y;
    const int rank = blockIdx.x;          // cluster_ctarank, 0..7
    const int tid  = threadIdx.x;
    const int lane = tid & 31;
    const int wid  = tid >> 5;

    const float* raw = raw_in + (size_t)b * NPTS * 3;
    float4* pb4 = g_pts4 + (size_t)b * NPTS;
    const int gbase = rank * (NPTS / FPS_BLKS);   // 8192 per CTA

    __shared__ float sc[4];
    __shared__ u64 wbk[32];
    __shared__ float4 wbc[32];
    __shared__ u64 slotk [2][FPS_BLKS];
    __shared__ u64 slotxy[2][FPS_BLKS];
    __shared__ u64 slotz [2][FPS_BLKS];
    __shared__ u64 mbar;

    if (tid == 0) {
        mbar_init(smem_u32(&mbar), FPS_BLKS);
        sc[0] = raw[0]; sc[1] = raw[1]; sc[2] = raw[2];   // start at index 0
    }
    __syncthreads();
    // all CTAs' mbarrier inits must be visible before any remote arrive (once)
    asm volatile("barrier.cluster.arrive.aligned;" ::: "memory");
    asm volatile("barrier.cluster.wait.aligned;"   ::: "memory");

    // ---- fused prep: load slice, p2 (XLA shape), publish g_pts4 ----
    float xs[FPS_PPT], ys[FPS_PPT], zs[FPS_PPT], md[FPS_PPT];
#pragma unroll
    for (int j = 0; j < FPS_PPT; j++) {
        int gi = gbase + j * FPS_THR + tid;
        xs[j] = raw[3 * gi + 0];
        ys[j] = raw[3 * gi + 1];
        zs[j] = raw[3 * gi + 2];
        md[j] = 3.402823466e38f;
        float p2 = __fmaf_rn(zs[j], zs[j], __fmaf_rn(ys[j], ys[j], __fmul_rn(xs[j], xs[j])));
        pb4[gi] = make_float4(xs[j], ys[j], zs[j], p2);
    }
    u64 pxk[4], pyk[4], pzk[4];
#pragma unroll
    for (int jj = 0; jj < 4; jj++) {
        pxk[jj] = pk2(xs[2 * jj], xs[2 * jj + 1]);
        pyk[jj] = pk2(ys[2 * jj], ys[2 * jj + 1]);
        pzk[jj] = pk2(zs[2 * jj], zs[2 * jj + 1]);
    }

    for (int iter = 0; iter < NPAT; iter++) {
        __syncthreads();   // sc valid
        float cx = sc[0], cy = sc[1], cz = sc[2];
        if (rank == 0 && tid == 0) {
            centers_out[(b * NPAT + iter) * 3 + 0] = cx;
            centers_out[(b * NPAT + iter) * 3 + 1] = cy;
            centers_out[(b * NPAT + iter) * 3 + 2] = cz;
        }
        if (iter == NPAT - 1) break;

        // --- packed update + argmax (r3-validated: add2/mul2 == scalar rn) ---
        u64 ncx = pk2(-cx, -cx), ncy = pk2(-cy, -cy), ncz = pk2(-cz, -cz);
        float bestv = -1.0f;
        u32   besti = 0;
#pragma unroll
        for (int jj = 0; jj < 4; jj++) {
            u64 dx = add2(pxk[jj], ncx);
            u64 dy = add2(pyk[jj], ncy);
            u64 dz = add2(pzk[jj], ncz);
            u64 s  = add2(add2(mul2(dx, dx), mul2(dy, dy)), mul2(dz, dz));
            float d0, d1; upk2(s, d0, d1);
            u32 gi0 = (u32)(gbase + 2 * jj * FPS_THR + tid);
            float m0 = fminf(md[2 * jj], d0);     md[2 * jj] = m0;
            if (m0 > bestv) { bestv = m0; besti = gi0; }
            float m1 = fminf(md[2 * jj + 1], d1); md[2 * jj + 1] = m1;
            if (m1 > bestv) { bestv = m1; besti = gi0 + FPS_THR; }
        }
        // candidate coords from OWN slice (own writes -> self-visible)
        float4 pc = pb4[besti];
        u64 key = ((u64)__float_as_uint(bestv) << 32) | (u32)(~besti);
        // warp reduce carrying coords
#pragma unroll
        for (int off = 16; off; off >>= 1) {
            u64   ok = __shfl_xor_sync(0xffffffffu, key, off);
            float ox = __shfl_xor_sync(0xffffffffu, pc.x, off);
            float oy = __shfl_xor_sync(0xffffffffu, pc.y, off);
            float oz = __shfl_xor_sync(0xffffffffu, pc.z, off);
            if (ok > key) { key = ok; pc.x = ox; pc.y = oy; pc.z = oz; }
        }
        if (lane == 0) { wbk[wid] = key; wbc[wid] = pc; }
        __syncthreads();

        const int par = iter & 1;
        if (wid == 0) {
            u64 k2 = wbk[lane];
            float4 c4 = wbc[lane];
#pragma unroll
            for (int off = 16; off; off >>= 1) {
                u64   ok = __shfl_xor_sync(0xffffffffu, k2, off);
                float ox = __shfl_xor_sync(0xffffffffu, c4.x, off);
                float oy = __shfl_xor_sync(0xffffffffu, c4.y, off);
                float oz = __shfl_xor_sync(0xffffffffu, c4.z, off);
                if (ok > k2) { k2 = ok; c4.x = ox; c4.y = oy; c4.z = oz; }
            }
            if (lane < FPS_BLKS) {   // push block best to peer 'lane'
                st_cluster_u64(mapa_u32(smem_u32(&slotk [par][rank]), (u32)lane), k2);
                st_cluster_u64(mapa_u32(smem_u32(&slotxy[par][rank]), (u32)lane), pk2(c4.x, c4.y));
                st_cluster_u64(mapa_u32(smem_u32(&slotz [par][rank]), (u32)lane), pk2(c4.z, 0.0f));
                mbar_arrive_cluster(mapa_u32(smem_u32(&mbar), (u32)lane));
            }
            mbar_wait_cluster(smem_u32(&mbar), (u32)par);
            if (lane < FPS_BLKS) {   // LOCAL reduce over the 8 pushed keys
                u64 s   = slotk [par][lane];
                u64 cxy = slotxy[par][lane];
                u64 cz2 = slotz [par][lane];
#pragma unroll
                for (int off = 4; off; off >>= 1) {
                    u64 ok = __shfl_xor_sync(0xffu, s,   off);
                    u64 oxy= __shfl_xor_sync(0xffu, cxy, off);
                    u64 oz = __shfl_xor_sync(0xffu, cz2, off);
                    if (ok > s) { s = ok; cxy = oxy; cz2 = oz; }
                }
                if (lane == 0) {
                    float wx, wy, wz, wpad;
                    upk2(cxy, wx, wy); upk2(cz2, wz, wpad);
                    sc[0] = wx; sc[1] = wy; sc[2] = wz;
                }
            }
        }
    }
}

// ---------------------------------------------------------------------------
// Kernel 2: exact KNN top-32. 1024 threads = 32 warps = 4 center-PAIRS x 8
// point-eighths (each warp gates 2 centers -> half the smem reads). Gate uses
// packed fma.rn.f32x2 (bitwise == scalar __fmaf_rn XLA shapes). Insert path:
// O(1) sorted insertion / bitonic fallback (unchanged, exact). 3-level merge.
// ---------------------------------------------------------------------------
__device__ __forceinline__ u64 bsort32(u64 v, int lane) {
#pragma unroll
    for (int k = 2; k <= 32; k <<= 1) {
#pragma unroll
        for (int j = k >> 1; j > 0; j >>= 1) {
            u64 o = __shfl_xor_sync(0xffffffffu, v, j);
            bool up      = ((lane & k) == 0);
            bool keepmin = (((lane & j) == 0) == up);
            bool smaller = (v < o);
            v = (smaller == keepmin) ? v : o;
        }
    }
    return v;
}
__device__ __forceinline__ u64 bmerge32(u64 v, int lane) {
#pragma unroll
    for (int j = 16; j > 0; j >>= 1) {
        u64 o = __shfl_xor_sync(0xffffffffu, v, j);
        bool keepmin = ((lane & j) == 0);
        bool smaller = (v < o);
        v = (smaller == keepmin) ? v : o;
    }
    return v;
}
__device__ __forceinline__ u32 flipf(float f) {
    u32 u = __float_as_uint(f);
    return u ^ ((u & 0x80000000u) ? 0xFFFFFFFFu : 0x80000000u);
}
__device__ __forceinline__ void insert4(u64& L, float& cm, const float* d2,
                                        u32 gi0, int lane) {
#pragma unroll
    for (int k = 0; k < 4; k++) {
        u32 mask = __ballot_sync(0xffffffffu, d2[k] <= cm);
        if (!mask) continue;
        u64 cand = ((u64)flipf(d2[k]) << 32) | (gi0 + (u32)k);
        if (__popc(mask) <= 8) {
            while (mask) {
                int src = __ffs(mask) - 1; mask &= mask - 1;
                u64 kk = __shfl_sync(0xffffffffu, cand, src);
                u64 up = __shfl_up_sync(0xffffffffu, L, 1);
                if (lane == 0) up = kk;
                u64 mx = (kk > up) ? kk : up;
                L = (L < kk) ? L : mx;
            }
        } else {
            u64 cs = bsort32(cand, lane);
            u64 o  = __shfl_sync(0xffffffffu, cs, 31 - lane);
            u64 m  = (L < o) ? L : o;
            L = bmerge32(m, lane);
        }
        u64 top = __shfl_sync(0xffffffffu, L, 31);
        u32 th = (u32)(top >> 32);
        th ^= (th & 0x80000000u) ? 0x80000000u : 0xFFFFFFFFu;
        cm = __uint_as_float(th);
    }
}

#define NE   8
#define C8   256
#define EPTS (NPTS / NE)   // 8192

__global__ void __launch_bounds__(1024, 1)
knn_kernel(const float* __restrict__ centers /* [NB][NPAT][3] */,
           float* __restrict__ patches_out   /* [NB][NPAT][KNN][3] */) {
    const int b    = blockIdx.y;      // 16
    const int grp  = blockIdx.x;      // 8 -> centers grp*8 .. grp*8+7
    const int tid  = threadIdx.x;
    const int lane = tid & 31;
    const int w    = tid >> 5;        // 0..31
    const int p    = w & 3;           // center pair 0..3
    const int e    = w >> 2;          // point eighth 0..7
    const int c0   = grp * 8 + 2 * p;
    const int c1   = c0 + 1;

    const float4* pbase = g_pts4 + (size_t)b * NPTS;

    const float cx0 = centers[(b * NPAT + c0) * 3 + 0];
    const float cy0 = centers[(b * NPAT + c0) * 3 + 1];
    const float cz0 = centers[(b * NPAT + c0) * 3 + 2];
    const float cx1 = centers[(b * NPAT + c1) * 3 + 0];
    const float cy1 = centers[(b * NPAT + c1) * 3 + 1];
    const float cz1 = centers[(b * NPAT + c1) * 3 + 2];
    const float c20 = __fmaf_rn(cz0, cz0, __fmaf_rn(cy0, cy0, __fmul_rn(cx0, cx0)));
    const float c21 = __fmaf_rn(cz1, cz1, __fmaf_rn(cy1, cy1, __fmul_rn(cx1, cx1)));
    const u64 cxx0 = pk2(cx0, cx0), cyy0 = pk2(cy0, cy0), czz0 = pk2(cz0, cz0), c2p0 = pk2(c20, c20);
    const u64 cxx1 = pk2(cx1, cx1), cyy1 = pk2(cy1, cy1), czz1 = pk2(cz1, cz1), c2p1 = pk2(c21, c21);
    const u64 neg2 = pk2(-2.0f, -2.0f);

    u64 L0 = 0xFF80000000000000ull, L1 = 0xFF80000000000000ull;
    float cm0 = __int_as_float(0x7f800000), cm1 = cm0;

    __shared__ float sxs[NE][C8], sys_[NE][C8], szs[NE][C8], sws[NE][C8];  // 32 KB
    __shared__ u64 smg[4][2][4][32];                                       // 8 KB

    for (int cb = 0; cb < EPTS; cb += C8) {
        __syncthreads();
        for (int t = tid; t < NE * C8; t += 1024) {
            int ee = t >> 8, i = t & (C8 - 1);
            float4 v = pbase[ee * EPTS + cb + i];
            sxs[ee][i] = v.x; sys_[ee][i] = v.y; szs[ee][i] = v.z; sws[ee][i] = v.w;
        }
        __syncthreads();
#pragma unroll
        for (int it = 0; it < 2; it++) {
            const int base = it * 128 + lane * 4;
            ulonglong2 X = *(const ulonglong2*)&sxs [e][base];
            ulonglong2 Y = *(const ulonglong2*)&sys_[e][base];
            ulonglong2 Z = *(const ulonglong2*)&szs [e][base];
            ulonglong2 W = *(const ulonglong2*)&sws [e][base];
            // XLA-shape d2 per lane-pair: fma2(-2, dot, c2 + p2)
            u64 dA0 = fma2(Z.x, czz0, fma2(Y.x, cyy0, mul2(X.x, cxx0)));
            u64 dB0 = fma2(Z.y, czz0, fma2(Y.y, cyy0, mul2(X.y, cxx0)));
            u64 eA0 = fma2(neg2, dA0, add2(c2p0, W.x));
            u64 eB0 = fma2(neg2, dB0, add2(c2p0, W.y));
            u64 dA1 = fma2(Z.x, czz1, fma2(Y.x, cyy1, mul2(X.x, cxx1)));
            u64 dB1 = fma2(Z.y, czz1, fma2(Y.y, cyy1, mul2(X.y, cxx1)));
            u64 eA1 = fma2(neg2, dA1, add2(c2p1, W.x));
            u64 eB1 = fma2(neg2, dB1, add2(c2p1, W.y));
            float d0[4], d1[4];
            upk2(eA0, d0[0], d0[1]); upk2(eB0, d0[2], d0[3]);
            upk2(eA1, d1[0], d1[1]); upk2(eB1, d1[2], d1[3]);
            float mn0 = fminf(fminf(d0[0], d0[1]), fminf(d0[2], d0[3]));
            float mn1 = fminf(fminf(d1[0], d1[1]), fminf(d1[2], d1[3]));
            bool go = (mn0 <= cm0) || (mn1 <= cm1);
            if (__any_sync(0xffffffffu, go)) {
                u32 gi0 = (u32)(e * EPTS + cb + base);
                insert4(L0, cm0, d0, gi0, lane);
                insert4(L1, cm1, d1, gi0, lane);
            }
        }
    }

    // ---- merge the 8 eighths per (pair, center): 3 levels ----
    __syncthreads();
    if (e & 1) { smg[p][0][e >> 1][lane] = L0; smg[p][1][e >> 1][lane] = L1; }
    __syncthreads();
    if (!(e & 1)) {
        u64 o0 = smg[p][0][e >> 1][31 - lane]; u64 m0 = (L0 < o0) ? L0 : o0; L0 = bmerge32(m0, lane);
        u64 o1 = smg[p][1][e >> 1][31 - lane]; u64 m1 = (L1 < o1) ? L1 : o1; L1 = bmerge32(m1, lane);
    }
    __syncthreads();
    if (e == 2 || e == 6) { smg[p][0][e >> 2][lane] = L0; smg[p][1][e >> 2][lane] = L1; }
    __syncthreads();
    if (e == 0 || e == 4) {
        int bi = (e + 2) >> 2;
        u64 o0 = smg[p][0][bi][31 - lane]; u64 m0 = (L0 < o0) ? L0 : o0; L0 = bmerge32(m0, lane);
        u64 o1 = smg[p][1][bi][31 - lane]; u64 m1 = (L1 < o1) ? L1 : o1; L1 = bmerge32(m1, lane);
    }
    __syncthreads();
    if (e == 4) { smg[p][0][0][lane] = L0; smg[p][1][0][lane] = L1; }
    __syncthreads();
    if (e == 0) {
        u64 o0 = smg[p][0][0][31 - lane]; u64 m0 = (L0 < o0) ? L0 : o0; L0 = bmerge32(m0, lane);
        u64 o1 = smg[p][1][0][31 - lane]; u64 m1 = (L1 < o1) ? L1 : o1; L1 = bmerge32(m1, lane);
        // lane == rank k: gather + subtract center (both centers of the pair)
        u32 g0 = (u32)L0;
        float4 q0 = pbase[g0];
        float* dst0 = patches_out + ((size_t)(b * NPAT + c0) * KNN + lane) * 3;
        dst0[0] = q0.x - cx0; dst0[1] = q0.y - cy0; dst0[2] = q0.z - cz0;
        u32 g1 = (u32)L1;
        float4 q1 = pbase[g1];
        float* dst1 = patches_out + ((size_t)(b * NPAT + c1) * KNN + lane) * 3;
        dst1[0] = q1.x - cx1; dst1[1] = q1.y - cy1; dst1[2] = q1.z - cz1;
    }
}

// ---------------------------------------------------------------------------
// Launch: fps (prep fused, cluster) -> knn. Graph-capturable, alloc-free.
// Replay-safe: no persistent inter-replay state (mbarriers are smem,
// re-inited every launch; all g_pts4 entries rewritten every launch).
// Output: tuple(patches, centers): [NB*NPAT*KNN*3] then [NB*NPAT*3]
// ---------------------------------------------------------------------------
extern "C" void kernel_launch(void* const* d_in, const int* in_sizes, int n_in,
                              void* d_out, int out_size) {
    const float* pts = (const float*)d_in[0];
    float* out      = (float*)d_out;
    float* patches  = out;                               // 16*64*32*3 = 98304
    float* centers  = out + (size_t)NB * NPAT * KNN * 3; // 16*64*3   =  3072

    fps_kernel<<<dim3(FPS_BLKS, NB), FPS_THR>>>(pts, centers);
    knn_kernel<<<dim3(8, NB), 1024>>>(centers, patches);
}

// round 9
// speedup vs baseline: 1.4812x; 1.4812x over previous
#include <cuda_runtime.h>
#include <cuda_bf16.h>
#include <cstdint>

// Problem constants
#define NB   16
#define NPTS 65536
#define NPAT 64      // NUM_PATCHES
#define KNN  32      // PATCH_SIZE

// FPS: 8 CTAs per batch, 1024 threads, 8 points per thread
#define FPS_BLKS   8
#define FPS_THR    1024
#define FPS_PPT    8
#define FPS_ARRIVALS (FPS_BLKS * 32)   // one red per warp = 256

typedef unsigned long long u64;
typedef unsigned int u32;

// Scratch (allocation-free rule: __device__ globals)
__device__ float4 g_pts4[NB * NPTS];                // x,y,z,|p|^2 (FMA-chain p2)
struct __align__(16) Slot { u64 key; u32 cnt; u32 pad; };
__device__ Slot g_slot[NB * NPAT];                  // per-(batch,iter) argmax slot
__device__ u64  g_kpart[NB * NPAT * 4 * KNN];       // per-(center,quarter) sorted top-32

// ---- packed f32x2 helpers (per-lane RN => bit-identical to scalar) ----
__device__ __forceinline__ u64 pk2(float a, float b) {
    u64 r; asm("mov.b64 %0,{%1,%2};" : "=l"(r) : "f"(a), "f"(b)); return r;
}
__device__ __forceinline__ void upk2(u64 v, float& a, float& b) {
    asm("mov.b64 {%0,%1},%2;" : "=f"(a), "=f"(b) : "l"(v));
}
__device__ __forceinline__ u64 add2(u64 a, u64 b) {
    u64 r; asm("add.rn.f32x2 %0,%1,%2;" : "=l"(r) : "l"(a), "l"(b)); return r;
}
__device__ __forceinline__ u64 mul2(u64 a, u64 b) {
    u64 r; asm("mul.rn.f32x2 %0,%1,%2;" : "=l"(r) : "l"(a), "l"(b)); return r;
}

// ---- atomic / ordered-memory helpers ----
__device__ __forceinline__ void red_max_u64(u64* p, u64 v) {
    asm volatile("red.relaxed.gpu.global.max.u64 [%0], %1;" :: "l"(p), "l"(v) : "memory");
}
__device__ __forceinline__ void red_add_rel_u32(u32* p, u32 v) {
    asm volatile("red.release.gpu.global.add.u32 [%0], %1;" :: "l"(p), "r"(v) : "memory");
}
__device__ __forceinline__ u32 ld_acq_u32(const u32* p) {
    u32 v; asm volatile("ld.acquire.gpu.global.u32 %0, [%1];" : "=r"(v) : "l"(p) : "memory");
    return v;
}
__device__ __forceinline__ u64 ld_cg_u64(const u64* p) {
    u64 v; asm volatile("ld.global.cg.u64 %0, [%1];" : "=l"(v) : "l"(p) : "memory");
    return v;
}

// ---------------------------------------------------------------------------
// Kernel 0: prep — pad points to float4 with p2, zero the FPS atomic slots.
// p2 uses the XLA/LLVM FP-contraction shape: fma(z,z, fma(y,y, x*x))
// ---------------------------------------------------------------------------
__global__ void prep_kernel(const float* __restrict__ pts) {
    int i = blockIdx.x * blockDim.x + threadIdx.x;   // 1,048,576 threads
    if (i < NB * NPAT) { g_slot[i].key = 0ull; g_slot[i].cnt = 0u; g_slot[i].pad = 0u; }
    float x = pts[3 * i + 0];
    float y = pts[3 * i + 1];
    float z = pts[3 * i + 2];
    float p2 = __fmaf_rn(z, z, __fmaf_rn(y, y, __fmul_rn(x, x)));
    g_pts4[i] = make_float4(x, y, z, p2);
}

// ---------------------------------------------------------------------------
// Kernel 1: FPS — 8 CTAs per batch, points+min_d in registers (packed f32x2,
// r3-validated bit-exact). Global argmax per iteration via red.max.u64 into a
// per-(batch,iter) slot + release-add arrival counter; one acquire-poller per
// CTA. No block-level second reduce, no store-visibility wait, no barriers
// beyond the CTA-local __syncthreads.
// ---------------------------------------------------------------------------
__global__ void __launch_bounds__(FPS_THR, 1)
fps_kernel(float* __restrict__ centers_out /* [NB][NPAT][3] */) {
    const int b    = blockIdx.y;
    const int sub  = blockIdx.x;          // 0..7
    const int tid  = threadIdx.x;
    const int lane = tid & 31;
    const int wid  = tid >> 5;            // 0..31

    const float4* pts = g_pts4 + (size_t)b * NPTS;
    Slot* slots = g_slot + (size_t)b * NPAT;
    const int gbase = sub * (NPTS / FPS_BLKS);   // 8192 per CTA

    // 8 points per thread as 4 packed pairs (lo: gi0, hi: gi0 + 1024)
    u64 pxk[4], pyk[4], pzk[4];
    float md[FPS_PPT];
#pragma unroll
    for (int jj = 0; jj < 4; jj++) {
        float4 p0 = pts[gbase + (2 * jj) * FPS_THR + tid];
        float4 p1 = pts[gbase + (2 * jj + 1) * FPS_THR + tid];
        pxk[jj] = pk2(p0.x, p1.x);
        pyk[jj] = pk2(p0.y, p1.y);
        pzk[jj] = pk2(p0.z, p1.z);
        md[2 * jj] = 3.402823466e38f;      // finfo(float32).max
        md[2 * jj + 1] = 3.402823466e38f;
    }

    __shared__ float sc[4];

    if (tid == 0) {   // deterministic start: point 0
        float4 c = pts[0];
        sc[0] = c.x; sc[1] = c.y; sc[2] = c.z;
    }

    for (int iter = 0; iter < NPAT; iter++) {
        __syncthreads();   // sc valid
        float cx = sc[0], cy = sc[1], cz = sc[2];
        if (sub == 0 && tid == 0) {
            centers_out[(b * NPAT + iter) * 3 + 0] = cx;
            centers_out[(b * NPAT + iter) * 3 + 1] = cy;
            centers_out[(b * NPAT + iter) * 3 + 2] = cz;
        }
        if (iter == NPAT - 1) break;   // last winner never consumed

        // --- packed update + argmax (bit-exact vs scalar non-fused chain) ---
        u64 ncx = pk2(-cx, -cx), ncy = pk2(-cy, -cy), ncz = pk2(-cz, -cz);
        float bestv = -1.0f;
        u32   besti = 0;
#pragma unroll
        for (int jj = 0; jj < 4; jj++) {
            u64 dx = add2(pxk[jj], ncx);
            u64 dy = add2(pyk[jj], ncy);
            u64 dz = add2(pzk[jj], ncz);
            u64 s  = add2(add2(mul2(dx, dx), mul2(dy, dy)), mul2(dz, dz));
            float d0, d1; upk2(s, d0, d1);
            u32 gi0 = (u32)(gbase + 2 * jj * FPS_THR + tid);
            float m0 = fminf(md[2 * jj], d0);     md[2 * jj] = m0;
            if (m0 > bestv) { bestv = m0; besti = gi0; }
            float m1 = fminf(md[2 * jj + 1], d1); md[2 * jj + 1] = m1;
            if (m1 > bestv) { bestv = m1; besti = gi0 + FPS_THR; }
        }
        // key: (d bits, ~idx) -> max == argmax, ties -> lowest index; key > 0
        u64 key = ((u64)__float_as_uint(bestv) << 32) | (u32)(~besti);
#pragma unroll
        for (int off = 16; off; off >>= 1) {
            u64 o = __shfl_xor_sync(0xffffffffu, key, off);
            if (o > key) key = o;
        }
        Slot* s = &slots[iter];
        if (lane == 0) {
            red_max_u64(&s->key, key);       // contribute warp max
            red_add_rel_u32(&s->cnt, 1u);    // release: orders the max before it
        }
        if (tid == 0) {
            // acquire-poll: all 256 release-adds seen => all maxes visible
            while (ld_acq_u32(&s->cnt) != FPS_ARRIVALS) {}
            u64 k = ld_cg_u64(&s->key);
            u32 wi = ~(u32)k;                // winning global index
            float4 c = pts[wi];              // L2-resident
            sc[0] = c.x; sc[1] = c.y; sc[2] = c.z;
        }
    }
}

// ---------------------------------------------------------------------------
// Kernel 2: exact KNN top-32, occupancy-tiled. 512 blocks x 512 threads
// (launch_bounds(512,3) -> 48 warps/SM). Block = (8 centers) x (1 quarter);
// 16 warps = 8 centers x 2 eighths. Gate: 4 pts/lane, XLA-shape d2; accepts
// via O(1) sorted insertion / bitonic fallback (r5-validated exact).
// Per-center quarter partial (sorted 32 u64) -> gmem; merge kernel finishes.
// ---------------------------------------------------------------------------
__device__ __forceinline__ u64 bsort32(u64 v, int lane) {
#pragma unroll
    for (int k = 2; k <= 32; k <<= 1) {
#pragma unroll
        for (int j = k >> 1; j > 0; j >>= 1) {
            u64 o = __shfl_xor_sync(0xffffffffu, v, j);
            bool up      = ((lane & k) == 0);
            bool keepmin = (((lane & j) == 0) == up);
            bool smaller = (v < o);
            v = (smaller == keepmin) ? v : o;
        }
    }
    return v;
}
__device__ __forceinline__ u64 bmerge32(u64 v, int lane) {
#pragma unroll
    for (int j = 16; j > 0; j >>= 1) {
        u64 o = __shfl_xor_sync(0xffffffffu, v, j);
        bool keepmin = ((lane & j) == 0);
        bool smaller = (v < o);
        v = (smaller == keepmin) ? v : o;
    }
    return v;
}
__device__ __forceinline__ u32 flipf(float f) {
    u32 u = __float_as_uint(f);
    return u ^ ((u & 0x80000000u) ? 0xFFFFFFFFu : 0x80000000u);
}

#define KCH  512             // points staged per eighth per chunk
#define E8   (NPTS / 8)      // 8192 points per eighth

__global__ void __launch_bounds__(512, 3)
knn_kernel(const float* __restrict__ centers /* [NB][NPAT][3] */) {
    const int b    = blockIdx.y;          // 16
    const int q    = blockIdx.x & 3;      // point quarter 0..3
    const int grp  = blockIdx.x >> 2;     // center group 0..7
    const int tid  = threadIdx.x;
    const int lane = tid & 31;
    const int w    = tid >> 5;            // 0..15
    const int cl   = w & 7;               // center within group
    const int h    = w >> 3;              // eighth-within-quarter 0/1
    const int c    = grp * 8 + cl;

    const float4* pbase = g_pts4 + (size_t)b * NPTS;

    const float cx = centers[(b * NPAT + c) * 3 + 0];
    const float cy = centers[(b * NPAT + c) * 3 + 1];
    const float cz = centers[(b * NPAT + c) * 3 + 2];
    const float c2 = __fmaf_rn(cz, cz, __fmaf_rn(cy, cy, __fmul_rn(cx, cx)));

    u64 L = 0xFF80000000000000ull;              // key for d2=+inf, idx 0
    float cm = __int_as_float(0x7f800000);      // +inf

    __shared__ float4 chunk[2][KCH];            // 16 KB
    __shared__ u64 sm2[8][32];                  // 2 KB (half merge)

    const int ebase = (2 * q + h) * E8;

    for (int cb = 0; cb < E8; cb += KCH) {
        __syncthreads();
        for (int t = tid; t < 2 * KCH; t += 512) {
            int hh = t >> 9, off = t & (KCH - 1);
            chunk[hh][off] = pbase[(2 * q + hh) * E8 + cb + off];
        }
        __syncthreads();

        const float4* my = chunk[h];
#pragma unroll 1
        for (int i = 0; i < KCH / 128; i++) {
            float4 pv[4];
            float d2[4];
#pragma unroll
            for (int k = 0; k < 4; k++) pv[k] = my[i * 128 + k * 32 + lane];
#pragma unroll
            for (int k = 0; k < 4; k++) {
                // XLA-shape d2: fma(-2, dot, c2+p2), dot = fma chain
                float dot = __fmaf_rn(pv[k].z, cz, __fmaf_rn(pv[k].y, cy, __fmul_rn(pv[k].x, cx)));
                d2[k] = __fmaf_rn(-2.0f, dot, __fadd_rn(c2, pv[k].w));
            }
            float mn = fminf(fminf(d2[0], d2[1]), fminf(d2[2], d2[3]));
            if (__any_sync(0xffffffffu, mn <= cm)) {
                u32 gi0 = (u32)(ebase + cb + i * 128 + lane);
#pragma unroll
                for (int k = 0; k < 4; k++) {
                    u32 mask = __ballot_sync(0xffffffffu, d2[k] <= cm);
                    if (!mask) continue;
                    u64 cand = ((u64)flipf(d2[k]) << 32) | (gi0 + (u32)(k * 32));
                    if (__popc(mask) <= 8) {
                        while (mask) {
                            int src = __ffs(mask) - 1; mask &= mask - 1;
                            u64 kk = __shfl_sync(0xffffffffu, cand, src);
                            u64 up = __shfl_up_sync(0xffffffffu, L, 1);
                            if (lane == 0) up = kk;
                            u64 mx = (kk > up) ? kk : up;
                            L = (L < kk) ? L : mx;
                        }
                    } else {
                        u64 cs = bsort32(cand, lane);
                        u64 o  = __shfl_sync(0xffffffffu, cs, 31 - lane);
                        u64 m  = (L < o) ? L : o;
                        L = bmerge32(m, lane);
                    }
                    u64 top = __shfl_sync(0xffffffffu, L, 31);
                    u32 th = (u32)(top >> 32);
                    th ^= (th & 0x80000000u) ? 0x80000000u : 0xFFFFFFFFu;
                    cm = __uint_as_float(th);
                }
            }
        }
    }

    // merge the two eighths of this quarter per center, write quarter partial
    __syncthreads();
    if (h == 1) sm2[cl][lane] = L;
    __syncthreads();
    if (h == 0) {
        u64 o = sm2[cl][31 - lane];
        u64 m = (L < o) ? L : o;
        L = bmerge32(m, lane);
        g_kpart[(((size_t)(b * NPAT + c)) * 4 + q) * KNN + lane] = L;
    }
}

// ---------------------------------------------------------------------------
// Kernel 3: merge the 4 quarter-partials per center (exact bitonic set-merge),
// gather neighbors, subtract center. 16 blocks x 1024 thr = 512 warps,
// 2 centers per warp.
// ---------------------------------------------------------------------------
__global__ void __launch_bounds__(1024, 1)
merge_kernel(const float* __restrict__ centers,
             float* __restrict__ patches_out /* [NB][NPAT][KNN][3] */) {
    const int b    = blockIdx.x;
    const int tid  = threadIdx.x;
    const int lane = tid & 31;
    const int w    = tid >> 5;   // 0..31

    const float4* pbase = g_pts4 + (size_t)b * NPTS;

    for (int c = w; c < NPAT; c += 32) {
        const u64* lists = g_kpart + ((size_t)(b * NPAT + c)) * 4 * KNN;
        u64 L = lists[lane];
#pragma unroll
        for (int j = 1; j < 4; j++) {
            u64 o = lists[j * KNN + (31 - lane)];
            u64 m = (L < o) ? L : o;
            L = bmerge32(m, lane);
        }
        const float cx = centers[(b * NPAT + c) * 3 + 0];
        const float cy = centers[(b * NPAT + c) * 3 + 1];
        const float cz = centers[(b * NPAT + c) * 3 + 2];
        u32 gi = (u32)L;
        float4 p = pbase[gi];
        float* dst = patches_out + ((size_t)(b * NPAT + c) * KNN + lane) * 3;
        dst[0] = p.x - cx;
        dst[1] = p.y - cy;
        dst[2] = p.z - cz;
    }
}

// ---------------------------------------------------------------------------
// Launch: prep -> fps -> knn -> merge. Graph-capturable, alloc-free.
// Replay-safe: prep re-zeroes g_slot at the START of every replay; g_kpart
// fully rewritten before merge reads it.
// Output: tuple(patches, centers): [NB*NPAT*KNN*3] then [NB*NPAT*3]
// ---------------------------------------------------------------------------
extern "C" void kernel_launch(void* const* d_in, const int* in_sizes, int n_in,
                              void* d_out, int out_size) {
    const float* pts = (const float*)d_in[0];
    float* out      = (float*)d_out;
    float* patches  = out;                               // 16*64*32*3 = 98304
    float* centers  = out + (size_t)NB * NPAT * KNN * 3; // 16*64*3   =  3072

    prep_kernel<<<4096, 256>>>(pts);
    fps_kernel<<<dim3(FPS_BLKS, NB), FPS_THR>>>(centers);
    knn_kernel<<<dim3(32, NB), 512>>>(centers);
    merge_kernel<<<NB, 1024>>>(centers, patches);
}

// round 10
// speedup vs baseline: 1.6030x; 1.0822x over previous
#include <cuda_runtime.h>
#include <cuda_bf16.h>
#include <cstdint>

// Problem constants
#define NB   16
#define NPTS 65536
#define NPAT 64      // NUM_PATCHES
#define KNN  32      // PATCH_SIZE

// FPS: 8 CTAs per batch, 1024 threads, 8 points per thread
#define FPS_BLKS   8
#define FPS_THR    1024
#define FPS_PPT    8

typedef unsigned long long u64;
typedef unsigned int u32;

// Scratch (allocation-free rule: __device__ globals)
__device__ float4 g_pts4[NB * NPTS];               // x,y,z,|p|^2 (FMA-chain p2)
__device__ u64    g_part[NB * NPAT * FPS_BLKS];    // per-(batch,iter,cta) argmax slot
__device__ u64    g_kpart[NB * NPAT * 4 * KNN];    // per-(center,quarter) sorted top-32

// ---- packed f32x2 helpers (per-lane RN => bit-identical to scalar) ----
__device__ __forceinline__ u64 pk2(float a, float b) {
    u64 r; asm("mov.b64 %0,{%1,%2};" : "=l"(r) : "f"(a), "f"(b)); return r;
}
__device__ __forceinline__ void upk2(u64 v, float& a, float& b) {
    asm("mov.b64 {%0,%1},%2;" : "=f"(a), "=f"(b) : "l"(v));
}
__device__ __forceinline__ u64 add2(u64 a, u64 b) {
    u64 r; asm("add.rn.f32x2 %0,%1,%2;" : "=l"(r) : "l"(a), "l"(b)); return r;
}
__device__ __forceinline__ u64 mul2(u64 a, u64 b) {
    u64 r; asm("mul.rn.f32x2 %0,%1,%2;" : "=l"(r) : "l"(a), "l"(b)); return r;
}

// ---------------------------------------------------------------------------
// Kernel 0: prep — pad points to float4 with p2, zero the FPS slots.
// p2 uses the XLA/LLVM FP-contraction shape: fma(z,z, fma(y,y, x*x)).
// Runs BEFORE fps: kernel ordering makes g_pts4 visible to all fps CTAs,
// so the fps handshake needs no acquire/release anywhere (volatile only).
// ---------------------------------------------------------------------------
__global__ void prep_kernel(const float* __restrict__ pts) {
    int i = blockIdx.x * blockDim.x + threadIdx.x;   // 1,048,576 threads
    if (i < NB * NPAT * FPS_BLKS) g_part[i] = 0ull;
    float x = pts[3 * i + 0];
    float y = pts[3 * i + 1];
    float z = pts[3 * i + 2];
    float p2 = __fmaf_rn(z, z, __fmaf_rn(y, y, __fmul_rn(x, x)));
    g_pts4[i] = make_float4(x, y, z, p2);
}

// ---------------------------------------------------------------------------
// Kernel 1: FPS — 8 CTAs per batch, points+min_d in registers (packed f32x2,
// bit-exact vs scalar non-fused chain; validated rel_err 0.0 in r3/r9).
// Handshake (empirically best family, r3): plain VOLATILE L2 slots.
//   - block reduce -> lane0 volatile-stores CTA key into slot[iter][sub]
//   - lanes 0-7 tight-poll all 8 slots in PARALLEL (volatile loads),
//     each prefetches its candidate's coords, 3-shfl reduce picks winner,
//     coords selected by ballot+shfl (winner LDG off the critical path).
// No atomics, no acquire, no nanosleep, no cluster barriers.
// ---------------------------------------------------------------------------
__global__ void __launch_bounds__(FPS_THR, 1)
fps_kernel(float* __restrict__ centers_out /* [NB][NPAT][3] */) {
    const int b    = blockIdx.y;
    const int sub  = blockIdx.x;          // 0..7
    const int tid  = threadIdx.x;
    const int lane = tid & 31;
    const int wid  = tid >> 5;            // 0..31

    const float4* pts = g_pts4 + (size_t)b * NPTS;
    volatile u64* part = (volatile u64*)(g_part + (size_t)b * NPAT * FPS_BLKS);
    const int gbase = sub * (NPTS / FPS_BLKS);   // 8192 per CTA

    // 8 points per thread as 4 packed pairs (lo: gi0, hi: gi0 + 1024)
    u64 pxk[4], pyk[4], pzk[4];
    float md[FPS_PPT];
#pragma unroll
    for (int jj = 0; jj < 4; jj++) {
        float4 p0 = pts[gbase + (2 * jj) * FPS_THR + tid];
        float4 p1 = pts[gbase + (2 * jj + 1) * FPS_THR + tid];
        pxk[jj] = pk2(p0.x, p1.x);
        pyk[jj] = pk2(p0.y, p1.y);
        pzk[jj] = pk2(p0.z, p1.z);
        md[2 * jj] = 3.402823466e38f;      // finfo(float32).max
        md[2 * jj + 1] = 3.402823466e38f;
    }

    __shared__ float sc[4];
    __shared__ u64 wb[32];

    if (tid == 0) {   // deterministic start: point 0
        float4 c = pts[0];
        sc[0] = c.x; sc[1] = c.y; sc[2] = c.z;
    }

    for (int iter = 0; iter < NPAT; iter++) {
        __syncthreads();   // sc valid
        float cx = sc[0], cy = sc[1], cz = sc[2];
        if (sub == 0 && tid == 0) {
            centers_out[(b * NPAT + iter) * 3 + 0] = cx;
            centers_out[(b * NPAT + iter) * 3 + 1] = cy;
            centers_out[(b * NPAT + iter) * 3 + 2] = cz;
        }
        if (iter == NPAT - 1) break;   // last winner never consumed

        // --- packed update + argmax (bit-exact vs scalar non-fused chain) ---
        u64 ncx = pk2(-cx, -cx), ncy = pk2(-cy, -cy), ncz = pk2(-cz, -cz);
        float bestv = -1.0f;
        u32   besti = 0;
#pragma unroll
        for (int jj = 0; jj < 4; jj++) {
            u64 dx = add2(pxk[jj], ncx);
            u64 dy = add2(pyk[jj], ncy);
            u64 dz = add2(pzk[jj], ncz);
            u64 s  = add2(add2(mul2(dx, dx), mul2(dy, dy)), mul2(dz, dz));
            float d0, d1; upk2(s, d0, d1);
            u32 gi0 = (u32)(gbase + 2 * jj * FPS_THR + tid);
            float m0 = fminf(md[2 * jj], d0);     md[2 * jj] = m0;
            if (m0 > bestv) { bestv = m0; besti = gi0; }
            float m1 = fminf(md[2 * jj + 1], d1); md[2 * jj + 1] = m1;
            if (m1 > bestv) { bestv = m1; besti = gi0 + FPS_THR; }
        }
        // key: (d bits, ~idx) -> max == argmax, ties -> lowest index; key > 0
        u64 key = ((u64)__float_as_uint(bestv) << 32) | (u32)(~besti);
#pragma unroll
        for (int off = 16; off; off >>= 1) {
            u64 o = __shfl_xor_sync(0xffffffffu, key, off);
            if (o > key) key = o;
        }
        if (lane == 0) wb[wid] = key;
        __syncthreads();
        if (wid == 0) {
            u64 v = wb[lane];
#pragma unroll
            for (int off = 16; off; off >>= 1) {
                u64 o = __shfl_xor_sync(0xffffffffu, v, off);
                if (o > v) v = o;
            }
            if (lane == 0) part[iter * FPS_BLKS + sub] = v;   // volatile store
            if (lane < FPS_BLKS) {
                u64 s;
                while ((s = part[iter * FPS_BLKS + lane]) == 0ull) {}  // tight poll
                u32 cand = ~(u32)s;
                float4 pc = pts[cand];        // prefetch candidate coords (L2)
                u64 m = s;
#pragma unroll
                for (int off = 4; off; off >>= 1) {
                    u64 o = __shfl_xor_sync(0xffu, m, off);
                    if (o > m) m = o;
                }
                u32 bal = __ballot_sync(0xffu, s == m);
                int src = __ffs(bal) - 1;     // winner's poller lane
                float wx = __shfl_sync(0xffu, pc.x, src);
                float wy = __shfl_sync(0xffu, pc.y, src);
                float wz = __shfl_sync(0xffu, pc.z, src);
                if (lane == 0) { sc[0] = wx; sc[1] = wy; sc[2] = wz; }
            }
        }
    }
}

// ---------------------------------------------------------------------------
// Kernel 2: exact KNN top-32, occupancy-tiled, REGISTER-LEAN (fits 40 regs ->
// true 3 blocks/SM = 48 warps). Block = (8 centers) x (1 quarter); 16 warps =
// 8 centers x 2 eighths. Gate: 4 pts/lane but only ONE point live at a time.
// Accepts: O(1) sorted insertion / bitonic fallback (validated exact).
// Per-center quarter partial (sorted 32 u64) -> gmem; merge kernel finishes.
// ---------------------------------------------------------------------------
__device__ __forceinline__ u64 bsort32(u64 v, int lane) {
#pragma unroll
    for (int k = 2; k <= 32; k <<= 1) {
#pragma unroll
        for (int j = k >> 1; j > 0; j >>= 1) {
            u64 o = __shfl_xor_sync(0xffffffffu, v, j);
            bool up      = ((lane & k) == 0);
            bool keepmin = (((lane & j) == 0) == up);
            bool smaller = (v < o);
            v = (smaller == keepmin) ? v : o;
        }
    }
    return v;
}
__device__ __forceinline__ u64 bmerge32(u64 v, int lane) {
#pragma unroll
    for (int j = 16; j > 0; j >>= 1) {
        u64 o = __shfl_xor_sync(0xffffffffu, v, j);
        bool keepmin = ((lane & j) == 0);
        bool smaller = (v < o);
        v = (smaller == keepmin) ? v : o;
    }
    return v;
}
__device__ __forceinline__ u32 flipf(float f) {
    u32 u = __float_as_uint(f);
    return u ^ ((u & 0x80000000u) ? 0xFFFFFFFFu : 0x80000000u);
}

#define KCH  512             // points staged per eighth per chunk
#define E8   (NPTS / 8)      // 8192 points per eighth

__global__ void __launch_bounds__(512, 3)
knn_kernel(const float* __restrict__ centers /* [NB][NPAT][3] */) {
    const int b    = blockIdx.y;          // 16
    const int q    = blockIdx.x & 3;      // point quarter 0..3
    const int grp  = blockIdx.x >> 2;     // center group 0..7
    const int tid  = threadIdx.x;
    const int lane = tid & 31;
    const int w    = tid >> 5;            // 0..15
    const int cl   = w & 7;               // center within group
    const int h    = w >> 3;              // eighth-within-quarter 0/1
    const int c    = grp * 8 + cl;

    const float4* pbase = g_pts4 + (size_t)b * NPTS;

    const float cx = centers[(b * NPAT + c) * 3 + 0];
    const float cy = centers[(b * NPAT + c) * 3 + 1];
    const float cz = centers[(b * NPAT + c) * 3 + 2];
    const float c2 = __fmaf_rn(cz, cz, __fmaf_rn(cy, cy, __fmul_rn(cx, cx)));

    u64 L = 0xFF80000000000000ull;              // key for d2=+inf, idx 0
    float cm = __int_as_float(0x7f800000);      // +inf

    __shared__ float4 chunk[2][KCH];            // 16 KB
    __shared__ u64 sm2[8][32];                  // 2 KB (half merge)

    const int ebase = (2 * q + h) * E8;

    for (int cb = 0; cb < E8; cb += KCH) {
        __syncthreads();
        for (int t = tid; t < 2 * KCH; t += 512) {
            int hh = t >> 9, off = t & (KCH - 1);
            chunk[hh][off] = pbase[(2 * q + hh) * E8 + cb + off];
        }
        __syncthreads();

        const float4* my = chunk[h];
#pragma unroll 1
        for (int i = 0; i < KCH / 128; i++) {
            float d2[4];
            // one point live at a time: load -> d2 -> discard (reg-lean)
#pragma unroll
            for (int k = 0; k < 4; k++) {
                float4 v = my[i * 128 + k * 32 + lane];
                // XLA-shape d2: fma(-2, dot, c2+p2), dot = fma chain
                float dot = __fmaf_rn(v.z, cz, __fmaf_rn(v.y, cy, __fmul_rn(v.x, cx)));
                d2[k] = __fmaf_rn(-2.0f, dot, __fadd_rn(c2, v.w));
            }
            float mn = fminf(fminf(d2[0], d2[1]), fminf(d2[2], d2[3]));
            if (__any_sync(0xffffffffu, mn <= cm)) {
#pragma unroll
                for (int k = 0; k < 4; k++) {
                    u32 mask = __ballot_sync(0xffffffffu, d2[k] <= cm);
                    if (!mask) continue;
                    u64 cand = ((u64)flipf(d2[k]) << 32)
                             | (u32)(ebase + cb + i * 128 + k * 32 + lane);
                    if (__popc(mask) <= 8) {
                        while (mask) {
                            int src = __ffs(mask) - 1; mask &= mask - 1;
                            u64 kk = __shfl_sync(0xffffffffu, cand, src);
                            u64 up = __shfl_up_sync(0xffffffffu, L, 1);
                            if (lane == 0) up = kk;
                            u64 mx = (kk > up) ? kk : up;
                            L = (L < kk) ? L : mx;
                        }
                    } else {
                        u64 cs = bsort32(cand, lane);
                        u64 o  = __shfl_sync(0xffffffffu, cs, 31 - lane);
                        u64 m  = (L < o) ? L : o;
                        L = bmerge32(m, lane);
                    }
                    u64 top = __shfl_sync(0xffffffffu, L, 31);
                    u32 th = (u32)(top >> 32);
                    th ^= (th & 0x80000000u) ? 0x80000000u : 0xFFFFFFFFu;
                    cm = __uint_as_float(th);
                }
            }
        }
    }

    // merge the two eighths of this quarter per center, write quarter partial
    __syncthreads();
    if (h == 1) sm2[cl][lane] = L;
    __syncthreads();
    if (h == 0) {
        u64 o = sm2[cl][31 - lane];
        u64 m = (L < o) ? L : o;
        L = bmerge32(m, lane);
        g_kpart[(((size_t)(b * NPAT + c)) * 4 + q) * KNN + lane] = L;
    }
}

// ---------------------------------------------------------------------------
// Kernel 3: merge the 4 quarter-partials per center (exact bitonic set-merge),
// gather neighbors, subtract center. 128 blocks x 256 thr = 1024 warps,
// one center per warp (max parallelism for this tiny kernel).
// ---------------------------------------------------------------------------
__global__ void __launch_bounds__(256, 4)
merge_kernel(const float* __restrict__ centers,
             float* __restrict__ patches_out /* [NB][NPAT][KNN][3] */) {
    const int b    = blockIdx.x >> 3;     // 16
    const int grp  = blockIdx.x & 7;      // 8
    const int tid  = threadIdx.x;
    const int lane = tid & 31;
    const int w    = tid >> 5;            // 0..7
    const int c    = grp * 8 + w;

    const float4* pbase = g_pts4 + (size_t)b * NPTS;

    const u64* lists = g_kpart + ((size_t)(b * NPAT + c)) * 4 * KNN;
    u64 L = lists[lane];
#pragma unroll
    for (int j = 1; j < 4; j++) {
        u64 o = lists[j * KNN + (31 - lane)];
        u64 m = (L < o) ? L : o;
        L = bmerge32(m, lane);
    }
    const float cx = centers[(b * NPAT + c) * 3 + 0];
    const float cy = centers[(b * NPAT + c) * 3 + 1];
    const float cz = centers[(b * NPAT + c) * 3 + 2];
    u32 gi = (u32)L;
    float4 p = pbase[gi];
    float* dst = patches_out + ((size_t)(b * NPAT + c) * KNN + lane) * 3;
    dst[0] = p.x - cx;
    dst[1] = p.y - cy;
    dst[2] = p.z - cz;
}

// ---------------------------------------------------------------------------
// Launch: prep -> fps -> knn -> merge. Graph-capturable, alloc-free.
// Replay-safe: prep re-zeroes g_part at the START of every replay; g_kpart
// fully rewritten before merge reads it.
// Output: tuple(patches, centers): [NB*NPAT*KNN*3] then [NB*NPAT*3]
// ---------------------------------------------------------------------------
extern "C" void kernel_launch(void* const* d_in, const int* in_sizes, int n_in,
                              void* d_out, int out_size) {
    const float* pts = (const float*)d_in[0];
    float* out      = (float*)d_out;
    float* patches  = out;                               // 16*64*32*3 = 98304
    float* centers  = out + (size_t)NB * NPAT * KNN * 3; // 16*64*3   =  3072

    prep_kernel<<<4096, 256>>>(pts);
    fps_kernel<<<dim3(FPS_BLKS, NB), FPS_THR>>>(centers);
    knn_kernel<<<dim3(32, NB), 512>>>(centers);
    merge_kernel<<<128, 256>>>(centers, patches);
}